// round 12
// baseline (speedup 1.0000x reference)
#include <cuda_runtime.h>
#include <mma.h>
#include <math.h>
#include <stdint.h>

using namespace nvcuda;

#define S_TOK 8192
#define MDIM  1024
#define HDIM  4096
#define NEXP  8
#define CAP   1024   // S/E, capacity 1.0, k=1

// ---------------- scratch (__device__ globals; no runtime alloc allowed) ----
// Referenced ONLY from device code (host-side symbol address is a stub — UB).
__device__ __align__(256) int   g_eidx[S_TOK];
__device__ __align__(256) float g_gval[S_TOK];
__device__ __align__(256) int   g_slot_token[NEXP * CAP];
__device__ __align__(256) float g_slot_gate[NEXP * CAP];
__device__ __align__(256) float g_h[(size_t)NEXP * CAP * HDIM];   // 128 MB hidden (gelu'd)

// ------------------------------- helpers -----------------------------------
__device__ __forceinline__ float gelu_exact(float v) {
    return 0.5f * v * (1.0f + erff(v * 0.70710678118654752440f));
}

// ---------------------------------------------------------------------------
// Gate: logits = x @ wg; softmax; argmax.   (proven)
// ---------------------------------------------------------------------------
__global__ __launch_bounds__(256)
void gate_kernel(const float* __restrict__ x, const float* __restrict__ wg) {
    __shared__ float swg[MDIM * NEXP];
    for (int i = threadIdx.x; i < MDIM * NEXP; i += blockDim.x) swg[i] = wg[i];
    __syncthreads();

    int warp = threadIdx.x >> 5;
    int lane = threadIdx.x & 31;
    int s = blockIdx.x * 8 + warp;
    if (s >= S_TOK) return;

    const float* xr = x + (size_t)s * MDIM;
    float acc[NEXP];
#pragma unroll
    for (int e = 0; e < NEXP; e++) acc[e] = 0.f;

    for (int k = lane; k < MDIM; k += 32) {
        float xv = xr[k];
#pragma unroll
        for (int e = 0; e < NEXP; e++) acc[e] += xv * swg[k * NEXP + e];
    }
#pragma unroll
    for (int e = 0; e < NEXP; e++) {
#pragma unroll
        for (int o = 16; o > 0; o >>= 1) acc[e] += __shfl_xor_sync(0xFFFFFFFFu, acc[e], o);
    }
    if (lane == 0) {
        float mx = acc[0];
        int mi = 0;
#pragma unroll
        for (int e = 1; e < NEXP; e++) {
            if (acc[e] > mx) { mx = acc[e]; mi = e; }
        }
        float den = 0.f;
#pragma unroll
        for (int e = 0; e < NEXP; e++) den += expf(acc[e] - mx);
        g_eidx[s] = mi;
        g_gval[s] = 1.0f / den;
    }
}

// ---------------------------------------------------------------------------
// Scan: exact in-order per-expert positions + capacity drop. (proven)
// ---------------------------------------------------------------------------
__global__ __launch_bounds__(256)
void scan_kernel() {
    __shared__ int cnt[256][NEXP + 1];
    int tid = threadIdx.x;

    for (int i = tid; i < NEXP * CAP; i += 256) {
        g_slot_token[i] = -1;
        g_slot_gate[i]  = 0.f;
    }

    int local[NEXP];
#pragma unroll
    for (int e = 0; e < NEXP; e++) local[e] = 0;

    int base = tid * 32;
    for (int t = 0; t < 32; t++) local[g_eidx[base + t]]++;
#pragma unroll
    for (int e = 0; e < NEXP; e++) cnt[tid][e] = local[e];
    __syncthreads();

    for (int off = 1; off < 256; off <<= 1) {
        int add[NEXP];
        if (tid >= off) {
#pragma unroll
            for (int e = 0; e < NEXP; e++) add[e] = cnt[tid - off][e];
        }
        __syncthreads();
        if (tid >= off) {
#pragma unroll
            for (int e = 0; e < NEXP; e++) cnt[tid][e] += add[e];
        }
        __syncthreads();
    }

    int run[NEXP];
#pragma unroll
    for (int e = 0; e < NEXP; e++) run[e] = cnt[tid][e] - local[e];

    for (int t = 0; t < 32; t++) {
        int s = base + t;
        int e = g_eidx[s];
        int p = run[e]++;
        if (p < CAP) {
            g_slot_token[e * CAP + p] = s;
            g_slot_gate[e * CAP + p]  = g_gval[s];
        }
    }
}

// ---------------------------------------------------------------------------
__global__ void zero_out_kernel(float4* __restrict__ out, int n4) {
    int i = blockIdx.x * blockDim.x + threadIdx.x;
    if (i < n4) out[i] = make_float4(0.f, 0.f, 0.f, 0.f);
}

// ---------------------------------------------------------------------------
// WMMA tf32 GEMM — round-11 mainloop, reshaped for occupancy:
// CTA tile 64x128, K-tile 32, single smem stage (27.7 KB), 128 threads
// (4 warps, warp tile 32x64 unchanged), __launch_bounds__(128, 4)
// -> 4 independent CTAs per SM (4 barrier domains) instead of 2.
// Fused epilogue via per-warp smem staging:
//   GATHER=true : g_h = gelu(acc + b1)
//   GATHER=false: out[tok] = gate*(acc + b2)   (scatter; dropped rows skipped)
// ---------------------------------------------------------------------------
#define A_LD 40     // 160 B row stride (mult of 32 B for wmma)
#define B_LD 136    // 544 B row stride (mult of 32 B)

template <int KDIM, int NTOT, bool GATHER>
__global__ __launch_bounds__(128, 4)
void wmma_gemm_kernel(const float* __restrict__ Xin,   // x (harness ptr); used iff GATHER
                      const float* __restrict__ Bw,    // weights [E][KDIM][NTOT]
                      const float* __restrict__ bias,  // [E][NTOT]
                      float* __restrict__ outp) {      // d_out; used iff !GATHER
    __shared__ __align__(32) float As[64][A_LD];       // 10.0 KB
    __shared__ __align__(32) float Bs[32][B_LD];       // 17.4 KB

    const int tid  = threadIdx.x;
    const int e    = blockIdx.y >> 4;                  // 16 row-tiles per expert
    const int row0 = (blockIdx.y & 15) * 64;
    const int n0   = blockIdx.x * 128;

    // A loader: 2 threads per row (64 rows), 16 floats (4x float4) each
    const int ar = tid >> 1;                 // 0..63
    const int ac = (tid & 1) * 16;           // 0 or 16
    const float* a_row;
    if constexpr (GATHER) {
        int tok = g_slot_token[e * CAP + row0 + ar];
        a_row = (tok >= 0) ? (Xin + (size_t)tok * KDIM) : nullptr;
    } else {
        a_row = g_h + (size_t)(e * CAP + row0 + ar) * KDIM;   // device-side ref
    }

    // B loader: 8 threads/row over 16 rows, 2 row-groups -> 32 rows, 16 fl each
    const int br = tid >> 3;                 // 0..15
    const int bc = (tid & 7) * 16;           // 0..112
    const float* b_row = Bw + (size_t)e * KDIM * NTOT + n0 + bc;

    const int wid = tid >> 5;                // 0..3
    const int wm  = (wid & 1) * 32;          // warp rows: 2 x 32
    const int wn  = (wid >> 1) * 64;         // warp cols: 2 x 64

    wmma::fragment<wmma::accumulator, 16, 16, 8, float> acc[2][4];
#pragma unroll
    for (int mm = 0; mm < 2; mm++)
#pragma unroll
        for (int nn = 0; nn < 4; nn++) wmma::fill_fragment(acc[mm][nn], 0.f);

    for (int kt = 0; kt < KDIM; kt += 32) {
        // ---- load A tile [64][32] ----
        if (a_row) {
#pragma unroll
            for (int i = 0; i < 4; i++) {
                float4 v = *(const float4*)(a_row + kt + ac + i * 4);
                As[ar][ac + i * 4 + 0] = wmma::__float_to_tf32(v.x);
                As[ar][ac + i * 4 + 1] = wmma::__float_to_tf32(v.y);
                As[ar][ac + i * 4 + 2] = wmma::__float_to_tf32(v.z);
                As[ar][ac + i * 4 + 3] = wmma::__float_to_tf32(v.w);
            }
        } else {
#pragma unroll
            for (int i = 0; i < 4; i++) {
                As[ar][ac + i * 4 + 0] = 0.f;
                As[ar][ac + i * 4 + 1] = 0.f;
                As[ar][ac + i * 4 + 2] = 0.f;
                As[ar][ac + i * 4 + 3] = 0.f;
            }
        }
        // ---- load B tile [32][128] (rows br and br+16) ----
#pragma unroll
        for (int g = 0; g < 2; g++) {
            const int r = br + g * 16;
            const float* bp = b_row + (size_t)(kt + r) * NTOT;
#pragma unroll
            for (int i = 0; i < 4; i++) {
                float4 v = *(const float4*)(bp + i * 4);
                Bs[r][bc + i * 4 + 0] = wmma::__float_to_tf32(v.x);
                Bs[r][bc + i * 4 + 1] = wmma::__float_to_tf32(v.y);
                Bs[r][bc + i * 4 + 2] = wmma::__float_to_tf32(v.z);
                Bs[r][bc + i * 4 + 3] = wmma::__float_to_tf32(v.w);
            }
        }
        __syncthreads();

#pragma unroll
        for (int k8 = 0; k8 < 4; k8++) {
            wmma::fragment<wmma::matrix_a, 16, 16, 8, wmma::precision::tf32, wmma::row_major> af[2];
            wmma::fragment<wmma::matrix_b, 16, 16, 8, wmma::precision::tf32, wmma::row_major> bf[4];
#pragma unroll
            for (int mm = 0; mm < 2; mm++)
                wmma::load_matrix_sync(af[mm], &As[wm + mm * 16][k8 * 8], A_LD);
#pragma unroll
            for (int nn = 0; nn < 4; nn++)
                wmma::load_matrix_sync(bf[nn], &Bs[k8 * 8][wn + nn * 16], B_LD);
#pragma unroll
            for (int mm = 0; mm < 2; mm++)
#pragma unroll
                for (int nn = 0; nn < 4; nn++)
                    wmma::mma_sync(acc[mm][nn], af[mm], bf[nn], acc[mm][nn]);
        }
        __syncthreads();
    }

    // ---------------- fused epilogue via per-warp smem staging --------------
    // As is free after the loop-end sync; 4 warps x 320 floats fits As (2560).
    float* stage = &As[0][0] + wid * 320;
    const int lane = tid & 31;
    const int r  = lane >> 1;                // staged row this thread handles
    const int cb = (lane & 1) * 8;           // 8 consecutive cols

#pragma unroll
    for (int mm = 0; mm < 2; mm++) {
        const int rowE = row0 + wm + mm * 16;
#pragma unroll
        for (int nn = 0; nn < 4; nn++) {
            wmma::store_matrix_sync(stage, acc[mm][nn], 20, wmma::mem_row_major);
            __syncwarp();
            const int col0 = n0 + wn + nn * 16;
            const float* bp = bias + (size_t)e * NTOT + col0;
            if constexpr (GATHER) {
                float* orow = g_h + (size_t)(e * CAP + rowE + r) * NTOT + col0;
#pragma unroll
                for (int i = 0; i < 8; i++) {
                    int c = cb + i;
                    orow[c] = gelu_exact(stage[r * 20 + c] + bp[c]);
                }
            } else {
                const int slotRow = e * CAP + rowE + r;
                const int tok = g_slot_token[slotRow];
                if (tok >= 0) {
                    const float gv = g_slot_gate[slotRow];
                    float* orow = outp + (size_t)tok * MDIM + col0;
#pragma unroll
                    for (int i = 0; i < 8; i++) {
                        int c = cb + i;
                        orow[c] = gv * (stage[r * 20 + c] + bp[c]);
                    }
                }
            }
            __syncwarp();                    // before next store overwrites stage
        }
    }
}

// ---------------------------------------------------------------------------
extern "C" void kernel_launch(void* const* d_in, const int* in_sizes, int n_in,
                              void* d_out, int out_size) {
    const float* x   = (const float*)d_in[0];   // [S, M]
    const float* wg  = (const float*)d_in[1];   // [M, E]
    const float* w1  = (const float*)d_in[2];   // [E, M, H]
    const float* b1  = (const float*)d_in[3];   // [E, H]
    const float* w2  = (const float*)d_in[4];   // [E, H, M]
    const float* b2  = (const float*)d_in[5];   // [E, M]
    float* out = (float*)d_out;                 // [S, M]

    gate_kernel<<<S_TOK / 8, 256>>>(x, wg);
    scan_kernel<<<1, 256>>>();

    int n4 = (S_TOK * MDIM) / 4;
    zero_out_kernel<<<(n4 + 255) / 256, 256>>>((float4*)out, n4);

    // GEMM1: g_h = gelu(gathered_x @ W1 + b1)   grid (32, 128)
    wmma_gemm_kernel<MDIM, HDIM, true><<<dim3(HDIM / 128, NEXP * 16), 128>>>(x, w1, b1, out);
    // GEMM2: out[tok] = gate * (g_h @ W2 + b2)  grid (8, 128)
    wmma_gemm_kernel<HDIM, MDIM, false><<<dim3(MDIM / 128, NEXP * 16), 128>>>(x, w2, b2, out);
}

// round 13
// speedup vs baseline: 1.0506x; 1.0506x over previous
#include <cuda_runtime.h>
#include <mma.h>
#include <math.h>
#include <stdint.h>

using namespace nvcuda;

#define S_TOK 8192
#define MDIM  1024
#define HDIM  4096
#define NEXP  8
#define CAP   1024   // S/E, capacity 1.0, k=1

// ---------------- scratch (__device__ globals; no runtime alloc allowed) ----
// Referenced ONLY from device code (host-side symbol address is a stub — UB).
__device__ __align__(256) int   g_eidx[S_TOK];
__device__ __align__(256) float g_gval[S_TOK];
__device__ __align__(256) int   g_slot_token[NEXP * CAP];
__device__ __align__(256) float g_slot_gate[NEXP * CAP];
__device__ __align__(256) float g_h[(size_t)NEXP * CAP * HDIM];   // 128 MB hidden (gelu'd)

// ------------------------------- helpers -----------------------------------
__device__ __forceinline__ float gelu_exact(float v) {
    return 0.5f * v * (1.0f + erff(v * 0.70710678118654752440f));
}
__device__ __forceinline__ float4 tf32x4(float4 v) {
    v.x = wmma::__float_to_tf32(v.x);
    v.y = wmma::__float_to_tf32(v.y);
    v.z = wmma::__float_to_tf32(v.z);
    v.w = wmma::__float_to_tf32(v.w);
    return v;
}

// ---------------------------------------------------------------------------
// Gate: logits = x @ wg; softmax; argmax.   (proven)
// ---------------------------------------------------------------------------
__global__ __launch_bounds__(256)
void gate_kernel(const float* __restrict__ x, const float* __restrict__ wg) {
    __shared__ float swg[MDIM * NEXP];
    for (int i = threadIdx.x; i < MDIM * NEXP; i += blockDim.x) swg[i] = wg[i];
    __syncthreads();

    int warp = threadIdx.x >> 5;
    int lane = threadIdx.x & 31;
    int s = blockIdx.x * 8 + warp;
    if (s >= S_TOK) return;

    const float* xr = x + (size_t)s * MDIM;
    float acc[NEXP];
#pragma unroll
    for (int e = 0; e < NEXP; e++) acc[e] = 0.f;

    for (int k = lane; k < MDIM; k += 32) {
        float xv = xr[k];
#pragma unroll
        for (int e = 0; e < NEXP; e++) acc[e] += xv * swg[k * NEXP + e];
    }
#pragma unroll
    for (int e = 0; e < NEXP; e++) {
#pragma unroll
        for (int o = 16; o > 0; o >>= 1) acc[e] += __shfl_xor_sync(0xFFFFFFFFu, acc[e], o);
    }
    if (lane == 0) {
        float mx = acc[0];
        int mi = 0;
#pragma unroll
        for (int e = 1; e < NEXP; e++) {
            if (acc[e] > mx) { mx = acc[e]; mi = e; }
        }
        float den = 0.f;
#pragma unroll
        for (int e = 0; e < NEXP; e++) den += expf(acc[e] - mx);
        g_eidx[s] = mi;
        g_gval[s] = 1.0f / den;
    }
}

// ---------------------------------------------------------------------------
// Scan: exact in-order per-expert positions + capacity drop. (proven)
// ---------------------------------------------------------------------------
__global__ __launch_bounds__(256)
void scan_kernel() {
    __shared__ int cnt[256][NEXP + 1];
    int tid = threadIdx.x;

    for (int i = tid; i < NEXP * CAP; i += 256) {
        g_slot_token[i] = -1;
        g_slot_gate[i]  = 0.f;
    }

    int local[NEXP];
#pragma unroll
    for (int e = 0; e < NEXP; e++) local[e] = 0;

    int base = tid * 32;
    for (int t = 0; t < 32; t++) local[g_eidx[base + t]]++;
#pragma unroll
    for (int e = 0; e < NEXP; e++) cnt[tid][e] = local[e];
    __syncthreads();

    for (int off = 1; off < 256; off <<= 1) {
        int add[NEXP];
        if (tid >= off) {
#pragma unroll
            for (int e = 0; e < NEXP; e++) add[e] = cnt[tid - off][e];
        }
        __syncthreads();
        if (tid >= off) {
#pragma unroll
            for (int e = 0; e < NEXP; e++) cnt[tid][e] += add[e];
        }
        __syncthreads();
    }

    int run[NEXP];
#pragma unroll
    for (int e = 0; e < NEXP; e++) run[e] = cnt[tid][e] - local[e];

    for (int t = 0; t < 32; t++) {
        int s = base + t;
        int e = g_eidx[s];
        int p = run[e]++;
        if (p < CAP) {
            g_slot_token[e * CAP + p] = s;
            g_slot_gate[e * CAP + p]  = g_gval[s];
        }
    }
}

// ---------------------------------------------------------------------------
__global__ void zero_out_kernel(float4* __restrict__ out, int n4) {
    int i = blockIdx.x * blockDim.x + threadIdx.x;
    if (i < n4) out[i] = make_float4(0.f, 0.f, 0.f, 0.f);
}

// ---------------------------------------------------------------------------
// WMMA tf32 GEMM — round-11 config (best: 2386us) with VECTORIZED smem fill:
// tf32-convert in registers, store as float4 (STS.128) -> 4x fewer STS ops.
// CTA tile 128x128, K-tile 32, single smem stage, 8 warps, 2 CTAs/SM.
// Fused epilogue (per-warp smem staging), vectorized gmem stores.
// ---------------------------------------------------------------------------
#define A_LD 40     // 160 B row stride (mult of 32 B for wmma; rows 16B-aligned)
#define B_LD 136    // 544 B row stride (mult of 32 B; rows 16B-aligned)

template <int KDIM, int NTOT, bool GATHER>
__global__ __launch_bounds__(256, 2)
void wmma_gemm_kernel(const float* __restrict__ Xin,   // x (harness ptr); used iff GATHER
                      const float* __restrict__ Bw,    // weights [E][KDIM][NTOT]
                      const float* __restrict__ bias,  // [E][NTOT]
                      float* __restrict__ outp) {      // d_out; used iff !GATHER
    __shared__ __align__(32) float As[128][A_LD];
    __shared__ __align__(32) float Bs[32][B_LD];

    const int tid  = threadIdx.x;
    const int e    = blockIdx.y >> 3;
    const int row0 = (blockIdx.y & 7) * 128;
    const int n0   = blockIdx.x * 128;

    // A loader: 2 threads per row, 16 floats (4x float4) each
    const int ar = tid >> 1;                 // 0..127
    const int ac = (tid & 1) * 16;           // 0 or 16
    const float* a_row;
    if constexpr (GATHER) {
        int tok = g_slot_token[e * CAP + row0 + ar];
        a_row = (tok >= 0) ? (Xin + (size_t)tok * KDIM) : nullptr;
    } else {
        a_row = g_h + (size_t)(e * CAP + row0 + ar) * KDIM;   // device-side ref
    }

    // B loader: 8 threads per row, 16 floats each
    const int br = tid >> 3;                 // 0..31
    const int bc = (tid & 7) * 16;           // 0..112
    const float* b_row = Bw + (size_t)e * KDIM * NTOT + n0 + bc;

    const int wid = tid >> 5;
    const int wm  = (wid & 3) * 32;
    const int wn  = (wid >> 2) * 64;

    wmma::fragment<wmma::accumulator, 16, 16, 8, float> acc[2][4];
#pragma unroll
    for (int mm = 0; mm < 2; mm++)
#pragma unroll
        for (int nn = 0; nn < 4; nn++) wmma::fill_fragment(acc[mm][nn], 0.f);

    const float4 zero4 = make_float4(0.f, 0.f, 0.f, 0.f);

    for (int kt = 0; kt < KDIM; kt += 32) {
        // ---- A tile [128][32]: LDG.128 -> cvt in regs -> STS.128 ----
#pragma unroll
        for (int i = 0; i < 4; i++) {
            float4 v = a_row ? tf32x4(*(const float4*)(a_row + kt + ac + i * 4)) : zero4;
            *(float4*)&As[ar][ac + i * 4] = v;
        }
        // ---- B tile [32][128]: same ----
        {
            const float* bp = b_row + (size_t)(kt + br) * NTOT;
#pragma unroll
            for (int i = 0; i < 4; i++) {
                float4 v = tf32x4(*(const float4*)(bp + i * 4));
                *(float4*)&Bs[br][bc + i * 4] = v;
            }
        }
        __syncthreads();

#pragma unroll
        for (int k8 = 0; k8 < 4; k8++) {
            wmma::fragment<wmma::matrix_a, 16, 16, 8, wmma::precision::tf32, wmma::row_major> af[2];
            wmma::fragment<wmma::matrix_b, 16, 16, 8, wmma::precision::tf32, wmma::row_major> bf[4];
#pragma unroll
            for (int mm = 0; mm < 2; mm++)
                wmma::load_matrix_sync(af[mm], &As[wm + mm * 16][k8 * 8], A_LD);
#pragma unroll
            for (int nn = 0; nn < 4; nn++)
                wmma::load_matrix_sync(bf[nn], &Bs[k8 * 8][wn + nn * 16], B_LD);
#pragma unroll
            for (int mm = 0; mm < 2; mm++)
#pragma unroll
                for (int nn = 0; nn < 4; nn++)
                    wmma::mma_sync(acc[mm][nn], af[mm], bf[nn], acc[mm][nn]);
        }
        __syncthreads();
    }

    // ---------------- fused epilogue via per-warp smem staging --------------
    // As storage is free after the loop-end sync; 8 warps x 320 floats.
    float* stage = &As[0][0] + wid * 320;
    const int lane = tid & 31;
    const int r  = lane >> 1;                // staged row this thread handles
    const int cb = (lane & 1) * 8;           // 8 consecutive cols

#pragma unroll
    for (int mm = 0; mm < 2; mm++) {
        const int rowE = row0 + wm + mm * 16;
#pragma unroll
        for (int nn = 0; nn < 4; nn++) {
            wmma::store_matrix_sync(stage, acc[mm][nn], 20, wmma::mem_row_major);
            __syncwarp();
            const int col0 = n0 + wn + nn * 16;
            const float* bp = bias + (size_t)e * NTOT + col0;
            if constexpr (GATHER) {
                float* orow = g_h + (size_t)(e * CAP + rowE + r) * NTOT + col0;
                float v[8];
#pragma unroll
                for (int i = 0; i < 8; i++)
                    v[i] = gelu_exact(stage[r * 20 + cb + i] + bp[cb + i]);
                *(float4*)(orow + cb)     = make_float4(v[0], v[1], v[2], v[3]);
                *(float4*)(orow + cb + 4) = make_float4(v[4], v[5], v[6], v[7]);
            } else {
                const int slotRow = e * CAP + rowE + r;
                const int tok = g_slot_token[slotRow];
                if (tok >= 0) {
                    const float gv = g_slot_gate[slotRow];
                    float* orow = outp + (size_t)tok * MDIM + col0;
                    float v[8];
#pragma unroll
                    for (int i = 0; i < 8; i++)
                        v[i] = gv * (stage[r * 20 + cb + i] + bp[cb + i]);
                    *(float4*)(orow + cb)     = make_float4(v[0], v[1], v[2], v[3]);
                    *(float4*)(orow + cb + 4) = make_float4(v[4], v[5], v[6], v[7]);
                }
            }
            __syncwarp();                    // before next store overwrites stage
        }
    }
}

// ---------------------------------------------------------------------------
extern "C" void kernel_launch(void* const* d_in, const int* in_sizes, int n_in,
                              void* d_out, int out_size) {
    const float* x   = (const float*)d_in[0];   // [S, M]
    const float* wg  = (const float*)d_in[1];   // [M, E]
    const float* w1  = (const float*)d_in[2];   // [E, M, H]
    const float* b1  = (const float*)d_in[3];   // [E, H]
    const float* w2  = (const float*)d_in[4];   // [E, H, M]
    const float* b2  = (const float*)d_in[5];   // [E, M]
    float* out = (float*)d_out;                 // [S, M]

    gate_kernel<<<S_TOK / 8, 256>>>(x, wg);
    scan_kernel<<<1, 256>>>();

    int n4 = (S_TOK * MDIM) / 4;
    zero_out_kernel<<<(n4 + 255) / 256, 256>>>((float4*)out, n4);

    // GEMM1: g_h = gelu(gathered_x @ W1 + b1)
    wmma_gemm_kernel<MDIM, HDIM, true><<<dim3(HDIM / 128, NEXP * 8), 256>>>(x, w1, b1, out);
    // GEMM2: out[tok] = gate * (g_h @ W2 + b2)
    wmma_gemm_kernel<HDIM, MDIM, false><<<dim3(MDIM / 128, NEXP * 8), 256>>>(x, w2, b2, out);
}